// round 16
// baseline (speedup 1.0000x reference)
#include <cuda_runtime.h>

#define NROWS (1 << 20)
#define NGROUPS (NROWS / 4)       // 262144 groups of 4 rows
#define TPS (NGROUPS / 4)         // stats passes: 65536 threads/slice; 4 quads (16 rows) each

// ---- device-global scratch ----
__device__ float g_accs[96];    // [0:32) pass1 (sum16,sumsq16); [32:96) pass2 (sum32,sumsq32)

// ---- packed f32x2 helpers ----
union F2U { float2 f; unsigned long long u; };
__device__ __forceinline__ float2 ffma2(float2 a, float2 b, float2 c) {
    F2U ua, ub, uc, r; ua.f = a; ub.f = b; uc.f = c;
    asm("fma.rn.f32x2 %0, %1, %2, %3;" : "=l"(r.u) : "l"(ua.u), "l"(ub.u), "l"(uc.u));
    return r.f;
}
__device__ __forceinline__ float2 fadd2(float2 a, float2 b) {
    F2U ua, ub, r; ua.f = a; ub.f = b;
    asm("add.rn.f32x2 %0, %1, %2;" : "=l"(r.u) : "l"(ua.u), "l"(ub.u));
    return r.f;
}
__device__ __forceinline__ float2 relu2(float2 a) {
    return make_float2(fmaxf(a.x, 0.f), fmaxf(a.y, 0.f));
}
__device__ __forceinline__ float2 dup2(float v) { return make_float2(v, v); }

// scalar non-coherent global loads with immediate offsets; destinations feed
// exactly one float2 lane each so ptxas can allocate them straight into
// aligned register pairs (no unpack MOVs).
__device__ __forceinline__ void load_quad_scalar(const float* __restrict__ base,
                                                 float2& X0, float2& X1, float2& X2,
                                                 float2& Y0, float2& Y1, float2& Y2) {
    asm("ld.global.nc.f32 %0, [%1+0];"  : "=f"(X0.x) : "l"(base));
    asm("ld.global.nc.f32 %0, [%1+4];"  : "=f"(X1.x) : "l"(base));
    asm("ld.global.nc.f32 %0, [%1+8];"  : "=f"(X2.x) : "l"(base));
    asm("ld.global.nc.f32 %0, [%1+12];" : "=f"(X0.y) : "l"(base));
    asm("ld.global.nc.f32 %0, [%1+16];" : "=f"(X1.y) : "l"(base));
    asm("ld.global.nc.f32 %0, [%1+20];" : "=f"(X2.y) : "l"(base));
    asm("ld.global.nc.f32 %0, [%1+24];" : "=f"(Y0.x) : "l"(base));
    asm("ld.global.nc.f32 %0, [%1+28];" : "=f"(Y1.x) : "l"(base));
    asm("ld.global.nc.f32 %0, [%1+32];" : "=f"(Y2.x) : "l"(base));
    asm("ld.global.nc.f32 %0, [%1+36];" : "=f"(Y0.y) : "l"(base));
    asm("ld.global.nc.f32 %0, [%1+40];" : "=f"(Y1.y) : "l"(base));
    asm("ld.global.nc.f32 %0, [%1+44];" : "=f"(Y2.y) : "l"(base));
}

__device__ __forceinline__ void conv1_h(float2 X0, float2 X1, float2 X2,
                                        float2 wa, float2 wb, float2 wc, float2 bi,
                                        float2& h0, float2& h1, float2& h2) {
    h0 = relu2(ffma2(wb, X0, ffma2(wc, X1, bi)));
    h1 = relu2(ffma2(wa, X0, ffma2(wb, X1, ffma2(wc, X2, bi))));
    h2 = relu2(ffma2(wa, X1, ffma2(wb, X2, bi)));
}
__device__ __forceinline__ void stat_acc(float2 h0, float2 h1, float2 h2,
                                         float2& s, float2& q) {
    s = fadd2(s, fadd2(fadd2(h0, h1), h2));
    q = ffma2(h0, h0, ffma2(h1, h1, ffma2(h2, h2, q)));
}

// BN1 fold, computed redundantly per block (threads < 16 then < 32)
__device__ __forceinline__ void fold1_to_shared(const float* __restrict__ g1,
                                                const float* __restrict__ bt1,
                                                const float* __restrict__ w2,
                                                const float* __restrict__ b2,
                                                int tid,
                                                float* a1s, float* c1s,
                                                float* sw2, float* sd2) {
    const float inv = 1.f / (3.f * (float)NROWS);
    if (tid < 16) {
        float m   = g_accs[tid] * inv;
        float var = g_accs[16 + tid] * inv - m * m;
        float a   = g1[tid] * rsqrtf(var + 1e-5f);
        a1s[tid] = a;
        c1s[tid] = bt1[tid] - m * a;
    }
    __syncthreads();
    if (tid < 32) {
        int ic = tid >> 1;
        float a = a1s[ic], c = c1s[ic];
        float w0 = w2[3*tid], wb = w2[3*tid+1], wc = w2[3*tid+2];
        sw2[3*tid+0] = w0 * a;
        sw2[3*tid+1] = wb * a;
        sw2[3*tid+2] = wc * a;
        float bb = b2[tid];
        sd2[3*tid+0] = bb + c * (wb + wc);        // t=0: taps k=1,2 in-bounds
        sd2[3*tid+1] = bb + c * (w0 + wb + wc);   // t=1: all taps
        sd2[3*tid+2] = bb + c * (w0 + wb);        // t=2: taps k=0,1 in-bounds
    }
}

// ------- pass 1: stats of relu(conv1+b1); 16 rows/thread; 4-ic slice -------
__global__ void __launch_bounds__(256) pass1_kernel(const float* __restrict__ x,
                                                    const float* __restrict__ w1,
                                                    const float* __restrict__ b1) {
    __shared__ float sw[48], sb[16];
    __shared__ float red[8 * 8];
    int tid = threadIdx.x;
    const int ic0 = 4 * blockIdx.y;
    if (tid < 48) sw[tid] = w1[tid];
    if (tid < 16) sb[tid] = b1[tid];
    __syncthreads();

    // 48 independent front-batched scalar loads (16 rows), lane-paired by allocator
    int t0 = blockIdx.x * 256 + tid;
    float2 P0[8], P1[8], P2[8];
#pragma unroll
    for (int k = 0; k < 4; k++) {
        const float* base = x + 12 * (t0 + k * TPS);
        load_quad_scalar(base, P0[2*k], P1[2*k], P2[2*k], P0[2*k+1], P1[2*k+1], P2[2*k+1]);
    }

    float2 Wa[4], Wb[4], Wc[4], Bi[4];
#pragma unroll
    for (int i = 0; i < 4; i++) {
        int c = ic0 + i;
        Wa[i] = dup2(sw[3*c]); Wb[i] = dup2(sw[3*c+1]);
        Wc[i] = dup2(sw[3*c+2]); Bi[i] = dup2(sb[c]);
    }

    float2 acc[8];                 // [0:4) sum, [4:8) sumsq
#pragma unroll
    for (int i = 0; i < 8; i++) acc[i] = make_float2(0.f, 0.f);

#pragma unroll
    for (int i = 0; i < 4; i++) {
#pragma unroll
        for (int p = 0; p < 8; p++) {
            float2 h0, h1, h2;
            conv1_h(P0[p], P1[p], P2[p], Wa[i], Wb[i], Wc[i], Bi[i], h0, h1, h2);
            stat_acc(h0, h1, h2, acc[i], acc[4+i]);
        }
    }

    int lane = tid & 31, warp = tid >> 5;
#pragma unroll
    for (int i = 0; i < 8; i++) {
        float v = acc[i].x + acc[i].y;
#pragma unroll
        for (int o = 16; o; o >>= 1) v += __shfl_down_sync(0xffffffffu, v, o);
        if (lane == 0) red[warp * 8 + i] = v;
    }
    __syncthreads();
    if (tid < 8) {
        float v = 0.f;
#pragma unroll
        for (int w = 0; w < 8; w++) v += red[w * 8 + tid];
        if (tid < 4) atomicAdd(&g_accs[ic0 + tid], v);
        else         atomicAdd(&g_accs[16 + ic0 + (tid - 4)], v);
    }
}

// ------- pass 2: inline BN1 fold + stats of relu(conv2+b2); 16 rows/thread; 2-ic slice -------
__global__ void __launch_bounds__(256) pass2_kernel(const float* __restrict__ x,
                                                    const float* __restrict__ w1,
                                                    const float* __restrict__ b1,
                                                    const float* __restrict__ g1,
                                                    const float* __restrict__ bt1,
                                                    const float* __restrict__ w2,
                                                    const float* __restrict__ b2) {
    __shared__ float sw[48], sb[16], sw2[96], sd2[96], a1s[16], c1s[16];
    __shared__ float red[8 * 8];
    int tid = threadIdx.x;
    const int ic0 = 2 * blockIdx.y;        // input channels [ic0, ic0+2)
    const int oc0 = 4 * blockIdx.y;        // output channels [oc0, oc0+4)
    if (tid < 48) sw[tid] = w1[tid];
    if (tid < 16) sb[tid] = b1[tid];
    fold1_to_shared(g1, bt1, w2, b2, tid, a1s, c1s, sw2, sd2);
    __syncthreads();

    // 48 independent front-batched scalar loads (16 rows)
    int t0 = blockIdx.x * 256 + tid;
    float2 P0[8], P1[8], P2[8];
#pragma unroll
    for (int k = 0; k < 4; k++) {
        const float* base = x + 12 * (t0 + k * TPS);
        load_quad_scalar(base, P0[2*k], P1[2*k], P2[2*k], P0[2*k+1], P1[2*k+1], P2[2*k+1]);
    }

    float2 Wa[2], Wb[2], Wc[2], Bi[2];
#pragma unroll
    for (int i = 0; i < 2; i++) {
        int c = ic0 + i;
        Wa[i] = dup2(sw[3*c]); Wb[i] = dup2(sw[3*c+1]);
        Wc[i] = dup2(sw[3*c+2]); Bi[i] = dup2(sb[c]);
    }
    float2 U0[4], Ub[4], Uc[4], D0[4], D1[4], D2[4];
#pragma unroll
    for (int k = 0; k < 4; k++) {
        int oc = oc0 + k;
        U0[k] = dup2(sw2[3*oc]); Ub[k] = dup2(sw2[3*oc+1]); Uc[k] = dup2(sw2[3*oc+2]);
        D0[k] = dup2(sd2[3*oc]); D1[k] = dup2(sd2[3*oc+1]); D2[k] = dup2(sd2[3*oc+2]);
    }

    float2 acc[8];                 // [0:4) sum, [4:8) sumsq for oc0+k
#pragma unroll
    for (int i = 0; i < 8; i++) acc[i] = make_float2(0.f, 0.f);

#pragma unroll
    for (int p = 0; p < 8; p++) {
#pragma unroll
        for (int i = 0; i < 2; i++) {
            float2 h0, h1, h2;
            conv1_h(P0[p], P1[p], P2[p], Wa[i], Wb[i], Wc[i], Bi[i], h0, h1, h2);
#pragma unroll
            for (int d = 0; d < 2; d++) {
                int k = 2*i + d;
                float2 t0v = relu2(ffma2(Ub[k], h0, ffma2(Uc[k], h1, D0[k])));
                float2 t1v = relu2(ffma2(U0[k], h0, ffma2(Ub[k], h1,
                                  ffma2(Uc[k], h2, D1[k]))));
                float2 t2v = relu2(ffma2(U0[k], h1, ffma2(Ub[k], h2, D2[k])));
                stat_acc(t0v, t1v, t2v, acc[k], acc[4+k]);
            }
        }
    }

    int lane = tid & 31, warp = tid >> 5;
#pragma unroll
    for (int i = 0; i < 8; i++) {
        float v = acc[i].x + acc[i].y;
#pragma unroll
        for (int o = 16; o; o >>= 1) v += __shfl_down_sync(0xffffffffu, v, o);
        if (lane == 0) red[warp * 8 + i] = v;
    }
    __syncthreads();
    if (tid < 8) {
        float v = 0.f;
#pragma unroll
        for (int w = 0; w < 8; w++) v += red[w * 8 + tid];
        if (tid < 4) atomicAdd(&g_accs[32 + oc0 + tid], v);
        else         atomicAdd(&g_accs[64 + oc0 + (tid - 4)], v);
    }
}

// ------- pass 3: inline fold1+fold2, fused forward, 4 rows (2 pairs)/thread -------
__global__ void __launch_bounds__(256) pass3_kernel(const float* __restrict__ x,
                                                    const float* __restrict__ w1,
                                                    const float* __restrict__ b1,
                                                    const float* __restrict__ g1,
                                                    const float* __restrict__ bt1,
                                                    const float* __restrict__ w2,
                                                    const float* __restrict__ b2,
                                                    const float* __restrict__ g2p,
                                                    const float* __restrict__ bt2,
                                                    const float* __restrict__ fw1,
                                                    const float* __restrict__ fb1,
                                                    const float* __restrict__ fw2,
                                                    const float* __restrict__ fb2,
                                                    float* __restrict__ out) {
    __shared__ float a1s[16], c1s[16];
    __shared__ float a2s[32], c2s[32];              // a2s holds a2/3
    __shared__ __align__(16) float4 sc1q[16 * 2];   // ic: (wa,wa,wb,wb), (wc,wc,bi,bi)
    __shared__ __align__(16) float4 sc2q[32 * 3];   // oc: (u0,u0,ub,ub),(uc,uc,d0,d0),(d1,d1,d2,d2)
    __shared__ __align__(16) float4 sfw4[32 * 8];   // oc: 8x (w2k,w2k,w2k+1,w2k+1)
    __shared__ float sfb1[16], sfw2[16];
    int tid = threadIdx.x;
    const float inv = 1.f / (3.f * (float)NROWS);

    // fold1 (BN1 -> conv2 weights) + BN2 params
    if (tid < 16) {
        float m   = g_accs[tid] * inv;
        float var = g_accs[16 + tid] * inv - m * m;
        float a   = g1[tid] * rsqrtf(var + 1e-5f);
        a1s[tid] = a;
        c1s[tid] = bt1[tid] - m * a;
    }
    if (tid >= 32 && tid < 64) {
        int t = tid - 32;
        float m   = g_accs[32 + t] * inv;
        float var = g_accs[64 + t] * inv - m * m;
        float a   = g2p[t] * rsqrtf(var + 1e-5f);
        a2s[t] = a * (1.f / 3.f);
        c2s[t] = bt2[t] - m * a;
    }
    if (tid < 16) {
        sc1q[2*tid+0] = make_float4(w1[3*tid],   w1[3*tid],   w1[3*tid+1], w1[3*tid+1]);
        sc1q[2*tid+1] = make_float4(w1[3*tid+2], w1[3*tid+2], b1[tid],     b1[tid]);
        sfw2[tid] = fw2[tid];
    }
    __syncthreads();
    if (tid < 32) {
        int ic = tid >> 1;
        float a = a1s[ic], c = c1s[ic];
        float w0 = w2[3*tid], wb = w2[3*tid+1], wc = w2[3*tid+2];
        float u0 = w0 * a, ub = wb * a, uc = wc * a;
        float bb = b2[tid];
        float d0 = bb + c * (wb + wc);
        float d1 = bb + c * (w0 + wb + wc);
        float d2 = bb + c * (w0 + wb);
        sc2q[3*tid+0] = make_float4(u0, u0, ub, ub);
        sc2q[3*tid+1] = make_float4(uc, uc, d0, d0);
        sc2q[3*tid+2] = make_float4(d1, d1, d2, d2);
    }
    for (int i = tid; i < 256; i += blockDim.x) {
        int oc = i >> 3, k = i & 7;
        float s = a2s[oc];
        float w0 = fw1[(2*k)   * 32 + oc] * s;
        float w1v = fw1[(2*k+1) * 32 + oc] * s;
        sfw4[i] = make_float4(w0, w0, w1v, w1v);
    }
    if (tid < 16) {
        float s = fb1[tid];
#pragma unroll
        for (int c = 0; c < 32; c++) s = fmaf(fw1[tid*32 + c], c2s[c], s);
        sfb1[tid] = s;
    }
    __syncthreads();
    const float fb2v = fb2[0];

    int g2 = blockIdx.x * blockDim.x + tid;      // group index; grid covers NGROUPS
    float2 X0, X1, X2, Y0, Y1, Y2;
    load_quad_scalar(x + 12 * g2, X0, X1, X2, Y0, Y1, Y2);

    float2 fA[16], fB[16];
#pragma unroll
    for (int j = 0; j < 16; j++) { float2 b = dup2(sfb1[j]); fA[j] = b; fB[j] = b; }

#pragma unroll 1
    for (int ic = 0; ic < 16; ic++) {
        float4 c1a = sc1q[2*ic], c1b = sc1q[2*ic+1];
        float2 wa = make_float2(c1a.x, c1a.y), wb = make_float2(c1a.z, c1a.w);
        float2 wc = make_float2(c1b.x, c1b.y), bi = make_float2(c1b.z, c1b.w);
        float2 hA0, hA1, hA2, hB0, hB1, hB2;
        conv1_h(X0, X1, X2, wa, wb, wc, bi, hA0, hA1, hA2);
        conv1_h(Y0, Y1, Y2, wa, wb, wc, bi, hB0, hB1, hB2);
#pragma unroll
        for (int d = 0; d < 2; d++) {
            int oc = 2*ic + d;
            float4 a = sc2q[3*oc], b = sc2q[3*oc+1], c = sc2q[3*oc+2];
            float2 u0 = make_float2(a.x, a.y), ub = make_float2(a.z, a.w);
            float2 uc = make_float2(b.x, b.y), d0 = make_float2(b.z, b.w);
            float2 d1 = make_float2(c.x, c.y), d2v = make_float2(c.z, c.w);
            float2 t0 = relu2(ffma2(ub, hA0, ffma2(uc, hA1, d0)));
            float2 t1 = relu2(ffma2(u0, hA0, ffma2(ub, hA1, ffma2(uc, hA2, d1))));
            float2 t2 = relu2(ffma2(u0, hA1, ffma2(ub, hA2, d2v)));
            float2 sA = fadd2(fadd2(t0, t1), t2);
            t0 = relu2(ffma2(ub, hB0, ffma2(uc, hB1, d0)));
            t1 = relu2(ffma2(u0, hB0, ffma2(ub, hB1, ffma2(uc, hB2, d1))));
            t2 = relu2(ffma2(u0, hB1, ffma2(ub, hB2, d2v)));
            float2 sB = fadd2(fadd2(t0, t1), t2);
#pragma unroll
            for (int k = 0; k < 8; k++) {
                float4 wq = sfw4[oc*8 + k];
                float2 w0 = make_float2(wq.x, wq.y), w1v = make_float2(wq.z, wq.w);
                fA[2*k]   = ffma2(w0,  sA, fA[2*k]);
                fA[2*k+1] = ffma2(w1v, sA, fA[2*k+1]);
                fB[2*k]   = ffma2(w0,  sB, fB[2*k]);
                fB[2*k+1] = ffma2(w1v, sB, fB[2*k+1]);
            }
        }
    }

    float o0 = fb2v, o1 = fb2v, o2 = fb2v, o3 = fb2v;
#pragma unroll
    for (int j = 0; j < 16; j++) {
        float wj = sfw2[j];
        o0 = fmaf(wj, fmaxf(fA[j].x, 0.f), o0);
        o1 = fmaf(wj, fmaxf(fA[j].y, 0.f), o1);
        o2 = fmaf(wj, fmaxf(fB[j].x, 0.f), o2);
        o3 = fmaf(wj, fmaxf(fB[j].y, 0.f), o3);
    }
    reinterpret_cast<float4*>(out)[g2] = make_float4(o0, o1, o2, o3);
}

extern "C" void kernel_launch(void* const* d_in, const int* in_sizes, int n_in,
                              void* d_out, int out_size) {
    const float* x   = (const float*)d_in[0];
    const float* w1  = (const float*)d_in[1];
    const float* b1  = (const float*)d_in[2];
    const float* g1  = (const float*)d_in[3];
    const float* bt1 = (const float*)d_in[4];
    const float* w2  = (const float*)d_in[5];
    const float* b2  = (const float*)d_in[6];
    const float* g2v = (const float*)d_in[7];
    const float* bt2 = (const float*)d_in[8];
    const float* fw1 = (const float*)d_in[9];
    const float* fb1 = (const float*)d_in[10];
    const float* fw2 = (const float*)d_in[11];
    const float* fb2 = (const float*)d_in[12];
    float* out = (float*)d_out;

    void* accs_ptr = nullptr;
    cudaGetSymbolAddress(&accs_ptr, g_accs);
    cudaMemsetAsync(accs_ptr, 0, 96 * sizeof(float));

    dim3 g1d(256, 4);
    pass1_kernel<<<g1d, 256>>>(x, w1, b1);
    dim3 g2d(256, 8);
    pass2_kernel<<<g2d, 256>>>(x, w1, b1, g1, bt1, w2, b2);
    pass3_kernel<<<NGROUPS / 256, 256>>>(x, w1, b1, g1, bt1, w2, b2,
                                         g2v, bt2, fw1, fb1, fw2, fb2, out);
}

// round 17
// speedup vs baseline: 1.0532x; 1.0532x over previous
#include <cuda_runtime.h>

#define NROWS (1 << 20)
#define NGROUPS (NROWS / 4)       // 262144 groups of 4 rows
#define TPS (NGROUPS / 4)         // stats passes: 65536 threads/slice; 4 quads (16 rows) each

// ---- device-global scratch ----
__device__ float g_accs[96];    // [0:32) pass1 (sum16,sumsq16); [32:96) pass2 (sum32,sumsq32)

// ---- packed f32x2 helpers ----
union F2U { float2 f; unsigned long long u; };
__device__ __forceinline__ float2 ffma2(float2 a, float2 b, float2 c) {
    F2U ua, ub, uc, r; ua.f = a; ub.f = b; uc.f = c;
    asm("fma.rn.f32x2 %0, %1, %2, %3;" : "=l"(r.u) : "l"(ua.u), "l"(ub.u), "l"(uc.u));
    return r.f;
}
__device__ __forceinline__ float2 fadd2(float2 a, float2 b) {
    F2U ua, ub, r; ua.f = a; ub.f = b;
    asm("add.rn.f32x2 %0, %1, %2;" : "=l"(r.u) : "l"(ua.u), "l"(ub.u));
    return r.f;
}
__device__ __forceinline__ float2 relu2(float2 a) {
    return make_float2(fmaxf(a.x, 0.f), fmaxf(a.y, 0.f));
}
__device__ __forceinline__ float2 dup2(float v) { return make_float2(v, v); }

// scalar non-coherent global loads with immediate offsets (pass1 only: wins there)
__device__ __forceinline__ void load_quad_scalar(const float* __restrict__ base,
                                                 float2& X0, float2& X1, float2& X2,
                                                 float2& Y0, float2& Y1, float2& Y2) {
    asm("ld.global.nc.f32 %0, [%1+0];"  : "=f"(X0.x) : "l"(base));
    asm("ld.global.nc.f32 %0, [%1+4];"  : "=f"(X1.x) : "l"(base));
    asm("ld.global.nc.f32 %0, [%1+8];"  : "=f"(X2.x) : "l"(base));
    asm("ld.global.nc.f32 %0, [%1+12];" : "=f"(X0.y) : "l"(base));
    asm("ld.global.nc.f32 %0, [%1+16];" : "=f"(X1.y) : "l"(base));
    asm("ld.global.nc.f32 %0, [%1+20];" : "=f"(X2.y) : "l"(base));
    asm("ld.global.nc.f32 %0, [%1+24];" : "=f"(Y0.x) : "l"(base));
    asm("ld.global.nc.f32 %0, [%1+28];" : "=f"(Y1.x) : "l"(base));
    asm("ld.global.nc.f32 %0, [%1+32];" : "=f"(Y2.x) : "l"(base));
    asm("ld.global.nc.f32 %0, [%1+36];" : "=f"(Y0.y) : "l"(base));
    asm("ld.global.nc.f32 %0, [%1+40];" : "=f"(Y1.y) : "l"(base));
    asm("ld.global.nc.f32 %0, [%1+44];" : "=f"(Y2.y) : "l"(base));
}

// unpack 3 float4 (12 consecutive floats = 4 rows) into 2 packed row-pairs
__device__ __forceinline__ void unpack_quad(float4 q0, float4 q1, float4 q2,
                                            float2& X0, float2& X1, float2& X2,
                                            float2& Y0, float2& Y1, float2& Y2) {
    X0 = make_float2(q0.x, q0.w); X1 = make_float2(q0.y, q1.x); X2 = make_float2(q0.z, q1.y);
    Y0 = make_float2(q1.z, q2.y); Y1 = make_float2(q1.w, q2.z); Y2 = make_float2(q2.x, q2.w);
}

__device__ __forceinline__ void conv1_h(float2 X0, float2 X1, float2 X2,
                                        float2 wa, float2 wb, float2 wc, float2 bi,
                                        float2& h0, float2& h1, float2& h2) {
    h0 = relu2(ffma2(wb, X0, ffma2(wc, X1, bi)));
    h1 = relu2(ffma2(wa, X0, ffma2(wb, X1, ffma2(wc, X2, bi))));
    h2 = relu2(ffma2(wa, X1, ffma2(wb, X2, bi)));
}
__device__ __forceinline__ void stat_acc(float2 h0, float2 h1, float2 h2,
                                         float2& s, float2& q) {
    s = fadd2(s, fadd2(fadd2(h0, h1), h2));
    q = ffma2(h0, h0, ffma2(h1, h1, ffma2(h2, h2, q)));
}

// BN1 fold, computed redundantly per block (threads < 16 then < 32)
__device__ __forceinline__ void fold1_to_shared(const float* __restrict__ g1,
                                                const float* __restrict__ bt1,
                                                const float* __restrict__ w2,
                                                const float* __restrict__ b2,
                                                int tid,
                                                float* a1s, float* c1s,
                                                float* sw2, float* sd2) {
    const float inv = 1.f / (3.f * (float)NROWS);
    if (tid < 16) {
        float m   = g_accs[tid] * inv;
        float var = g_accs[16 + tid] * inv - m * m;
        float a   = g1[tid] * rsqrtf(var + 1e-5f);
        a1s[tid] = a;
        c1s[tid] = bt1[tid] - m * a;
    }
    __syncthreads();
    if (tid < 32) {
        int ic = tid >> 1;
        float a = a1s[ic], c = c1s[ic];
        float w0 = w2[3*tid], wb = w2[3*tid+1], wc = w2[3*tid+2];
        sw2[3*tid+0] = w0 * a;
        sw2[3*tid+1] = wb * a;
        sw2[3*tid+2] = wc * a;
        float bb = b2[tid];
        sd2[3*tid+0] = bb + c * (wb + wc);        // t=0: taps k=1,2 in-bounds
        sd2[3*tid+1] = bb + c * (w0 + wb + wc);   // t=1: all taps
        sd2[3*tid+2] = bb + c * (w0 + wb);        // t=2: taps k=0,1 in-bounds
    }
}

// ------- pass 1: stats of relu(conv1+b1); 16 rows/thread; 4-ic slice; scalar loads -------
__global__ void __launch_bounds__(256) pass1_kernel(const float* __restrict__ x,
                                                    const float* __restrict__ w1,
                                                    const float* __restrict__ b1) {
    __shared__ float sw[48], sb[16];
    __shared__ float red[8 * 8];
    int tid = threadIdx.x;
    const int ic0 = 4 * blockIdx.y;
    if (tid < 48) sw[tid] = w1[tid];
    if (tid < 16) sb[tid] = b1[tid];
    __syncthreads();

    // 48 independent front-batched scalar loads (16 rows), lane-paired by allocator
    int t0 = blockIdx.x * 256 + tid;
    float2 P0[8], P1[8], P2[8];
#pragma unroll
    for (int k = 0; k < 4; k++) {
        const float* base = x + 12 * (t0 + k * TPS);
        load_quad_scalar(base, P0[2*k], P1[2*k], P2[2*k], P0[2*k+1], P1[2*k+1], P2[2*k+1]);
    }

    float2 Wa[4], Wb[4], Wc[4], Bi[4];
#pragma unroll
    for (int i = 0; i < 4; i++) {
        int c = ic0 + i;
        Wa[i] = dup2(sw[3*c]); Wb[i] = dup2(sw[3*c+1]);
        Wc[i] = dup2(sw[3*c+2]); Bi[i] = dup2(sb[c]);
    }

    float2 acc[8];                 // [0:4) sum, [4:8) sumsq
#pragma unroll
    for (int i = 0; i < 8; i++) acc[i] = make_float2(0.f, 0.f);

#pragma unroll
    for (int i = 0; i < 4; i++) {
#pragma unroll
        for (int p = 0; p < 8; p++) {
            float2 h0, h1, h2;
            conv1_h(P0[p], P1[p], P2[p], Wa[i], Wb[i], Wc[i], Bi[i], h0, h1, h2);
            stat_acc(h0, h1, h2, acc[i], acc[4+i]);
        }
    }

    int lane = tid & 31, warp = tid >> 5;
#pragma unroll
    for (int i = 0; i < 8; i++) {
        float v = acc[i].x + acc[i].y;
#pragma unroll
        for (int o = 16; o; o >>= 1) v += __shfl_down_sync(0xffffffffu, v, o);
        if (lane == 0) red[warp * 8 + i] = v;
    }
    __syncthreads();
    if (tid < 8) {
        float v = 0.f;
#pragma unroll
        for (int w = 0; w < 8; w++) v += red[w * 8 + tid];
        if (tid < 4) atomicAdd(&g_accs[ic0 + tid], v);
        else         atomicAdd(&g_accs[16 + ic0 + (tid - 4)], v);
    }
}

// ------- pass 2: inline BN1 fold + stats of relu(conv2+b2); 16 rows/thread; 2-ic slice -------
__global__ void __launch_bounds__(256) pass2_kernel(const float* __restrict__ x,
                                                    const float* __restrict__ w1,
                                                    const float* __restrict__ b1,
                                                    const float* __restrict__ g1,
                                                    const float* __restrict__ bt1,
                                                    const float* __restrict__ w2,
                                                    const float* __restrict__ b2) {
    __shared__ float sw[48], sb[16], sw2[96], sd2[96], a1s[16], c1s[16];
    __shared__ float red[8 * 8];
    int tid = threadIdx.x;
    const int ic0 = 2 * blockIdx.y;        // input channels [ic0, ic0+2)
    const int oc0 = 4 * blockIdx.y;        // output channels [oc0, oc0+4)
    if (tid < 48) sw[tid] = w1[tid];
    if (tid < 16) sb[tid] = b1[tid];
    fold1_to_shared(g1, bt1, w2, b2, tid, a1s, c1s, sw2, sd2);
    __syncthreads();

    // 12 independent front-batched LDG.128 (16 rows)
    int t0 = blockIdx.x * 256 + tid;
    const float4* x4 = reinterpret_cast<const float4*>(x);
    float4 q[12];
#pragma unroll
    for (int k = 0; k < 4; k++) {
        int g = t0 + k * TPS;
        q[3*k] = x4[3*g]; q[3*k+1] = x4[3*g+1]; q[3*k+2] = x4[3*g+2];
    }

    float2 Wa[2], Wb[2], Wc[2], Bi[2];
#pragma unroll
    for (int i = 0; i < 2; i++) {
        int c = ic0 + i;
        Wa[i] = dup2(sw[3*c]); Wb[i] = dup2(sw[3*c+1]);
        Wc[i] = dup2(sw[3*c+2]); Bi[i] = dup2(sb[c]);
    }
    float2 U0[4], Ub[4], Uc[4], D0[4], D1[4], D2[4];
#pragma unroll
    for (int k = 0; k < 4; k++) {
        int oc = oc0 + k;
        U0[k] = dup2(sw2[3*oc]); Ub[k] = dup2(sw2[3*oc+1]); Uc[k] = dup2(sw2[3*oc+2]);
        D0[k] = dup2(sd2[3*oc]); D1[k] = dup2(sd2[3*oc+1]); D2[k] = dup2(sd2[3*oc+2]);
    }

    float2 P0[8], P1[8], P2[8];
#pragma unroll
    for (int k = 0; k < 4; k++)
        unpack_quad(q[3*k], q[3*k+1], q[3*k+2],
                    P0[2*k], P1[2*k], P2[2*k], P0[2*k+1], P1[2*k+1], P2[2*k+1]);

    float2 acc[8];                 // [0:4) sum, [4:8) sumsq for oc0+k
#pragma unroll
    for (int i = 0; i < 8; i++) acc[i] = make_float2(0.f, 0.f);

#pragma unroll
    for (int p = 0; p < 8; p++) {
#pragma unroll
        for (int i = 0; i < 2; i++) {
            float2 h0, h1, h2;
            conv1_h(P0[p], P1[p], P2[p], Wa[i], Wb[i], Wc[i], Bi[i], h0, h1, h2);
#pragma unroll
            for (int d = 0; d < 2; d++) {
                int k = 2*i + d;
                float2 t0v = relu2(ffma2(Ub[k], h0, ffma2(Uc[k], h1, D0[k])));
                float2 t1v = relu2(ffma2(U0[k], h0, ffma2(Ub[k], h1,
                                  ffma2(Uc[k], h2, D1[k]))));
                float2 t2v = relu2(ffma2(U0[k], h1, ffma2(Ub[k], h2, D2[k])));
                stat_acc(t0v, t1v, t2v, acc[k], acc[4+k]);
            }
        }
    }

    int lane = tid & 31, warp = tid >> 5;
#pragma unroll
    for (int i = 0; i < 8; i++) {
        float v = acc[i].x + acc[i].y;
#pragma unroll
        for (int o = 16; o; o >>= 1) v += __shfl_down_sync(0xffffffffu, v, o);
        if (lane == 0) red[warp * 8 + i] = v;
    }
    __syncthreads();
    if (tid < 8) {
        float v = 0.f;
#pragma unroll
        for (int w = 0; w < 8; w++) v += red[w * 8 + tid];
        if (tid < 4) atomicAdd(&g_accs[32 + oc0 + tid], v);
        else         atomicAdd(&g_accs[64 + oc0 + (tid - 4)], v);
    }
}

// ------- pass 3: inline fold1+fold2, fused forward, 4 rows (2 pairs)/thread -------
__global__ void __launch_bounds__(256) pass3_kernel(const float* __restrict__ x,
                                                    const float* __restrict__ w1,
                                                    const float* __restrict__ b1,
                                                    const float* __restrict__ g1,
                                                    const float* __restrict__ bt1,
                                                    const float* __restrict__ w2,
                                                    const float* __restrict__ b2,
                                                    const float* __restrict__ g2p,
                                                    const float* __restrict__ bt2,
                                                    const float* __restrict__ fw1,
                                                    const float* __restrict__ fb1,
                                                    const float* __restrict__ fw2,
                                                    const float* __restrict__ fb2,
                                                    float* __restrict__ out) {
    __shared__ float a1s[16], c1s[16];
    __shared__ float a2s[32], c2s[32];              // a2s holds a2/3
    __shared__ __align__(16) float4 sc1q[16 * 2];   // ic: (wa,wa,wb,wb), (wc,wc,bi,bi)
    __shared__ __align__(16) float4 sc2q[32 * 3];   // oc: (u0,u0,ub,ub),(uc,uc,d0,d0),(d1,d1,d2,d2)
    __shared__ __align__(16) float4 sfw4[32 * 8];   // oc: 8x (w2k,w2k,w2k+1,w2k+1)
    __shared__ float sfb1[16], sfw2[16];
    int tid = threadIdx.x;
    const float inv = 1.f / (3.f * (float)NROWS);

    // fold1 (BN1 -> conv2 weights) + BN2 params
    if (tid < 16) {
        float m   = g_accs[tid] * inv;
        float var = g_accs[16 + tid] * inv - m * m;
        float a   = g1[tid] * rsqrtf(var + 1e-5f);
        a1s[tid] = a;
        c1s[tid] = bt1[tid] - m * a;
    }
    if (tid >= 32 && tid < 64) {
        int t = tid - 32;
        float m   = g_accs[32 + t] * inv;
        float var = g_accs[64 + t] * inv - m * m;
        float a   = g2p[t] * rsqrtf(var + 1e-5f);
        a2s[t] = a * (1.f / 3.f);
        c2s[t] = bt2[t] - m * a;
    }
    if (tid < 16) {
        sc1q[2*tid+0] = make_float4(w1[3*tid],   w1[3*tid],   w1[3*tid+1], w1[3*tid+1]);
        sc1q[2*tid+1] = make_float4(w1[3*tid+2], w1[3*tid+2], b1[tid],     b1[tid]);
        sfw2[tid] = fw2[tid];
    }
    __syncthreads();
    if (tid < 32) {
        int ic = tid >> 1;
        float a = a1s[ic], c = c1s[ic];
        float w0 = w2[3*tid], wb = w2[3*tid+1], wc = w2[3*tid+2];
        float u0 = w0 * a, ub = wb * a, uc = wc * a;
        float bb = b2[tid];
        float d0 = bb + c * (wb + wc);
        float d1 = bb + c * (w0 + wb + wc);
        float d2 = bb + c * (w0 + wb);
        sc2q[3*tid+0] = make_float4(u0, u0, ub, ub);
        sc2q[3*tid+1] = make_float4(uc, uc, d0, d0);
        sc2q[3*tid+2] = make_float4(d1, d1, d2, d2);
    }
    for (int i = tid; i < 256; i += blockDim.x) {
        int oc = i >> 3, k = i & 7;
        float s = a2s[oc];
        float w0 = fw1[(2*k)   * 32 + oc] * s;
        float w1v = fw1[(2*k+1) * 32 + oc] * s;
        sfw4[i] = make_float4(w0, w0, w1v, w1v);
    }
    if (tid < 16) {
        float s = fb1[tid];
#pragma unroll
        for (int c = 0; c < 32; c++) s = fmaf(fw1[tid*32 + c], c2s[c], s);
        sfb1[tid] = s;
    }
    __syncthreads();
    const float fb2v = fb2[0];

    int g2 = blockIdx.x * blockDim.x + tid;      // group index; grid covers NGROUPS
    const float4* x4 = reinterpret_cast<const float4*>(x);
    float4 q0 = x4[3*g2], q1 = x4[3*g2+1], q2 = x4[3*g2+2];
    float2 X0, X1, X2, Y0, Y1, Y2;
    unpack_quad(q0, q1, q2, X0, X1, X2, Y0, Y1, Y2);

    float2 fA[16], fB[16];
#pragma unroll
    for (int j = 0; j < 16; j++) { float2 b = dup2(sfb1[j]); fA[j] = b; fB[j] = b; }

#pragma unroll 1
    for (int ic = 0; ic < 16; ic++) {
        float4 c1a = sc1q[2*ic], c1b = sc1q[2*ic+1];
        float2 wa = make_float2(c1a.x, c1a.y), wb = make_float2(c1a.z, c1a.w);
        float2 wc = make_float2(c1b.x, c1b.y), bi = make_float2(c1b.z, c1b.w);
        float2 hA0, hA1, hA2, hB0, hB1, hB2;
        conv1_h(X0, X1, X2, wa, wb, wc, bi, hA0, hA1, hA2);
        conv1_h(Y0, Y1, Y2, wa, wb, wc, bi, hB0, hB1, hB2);
#pragma unroll
        for (int d = 0; d < 2; d++) {
            int oc = 2*ic + d;
            float4 a = sc2q[3*oc], b = sc2q[3*oc+1], c = sc2q[3*oc+2];
            float2 u0 = make_float2(a.x, a.y), ub = make_float2(a.z, a.w);
            float2 uc = make_float2(b.x, b.y), d0 = make_float2(b.z, b.w);
            float2 d1 = make_float2(c.x, c.y), d2v = make_float2(c.z, c.w);
            float2 t0 = relu2(ffma2(ub, hA0, ffma2(uc, hA1, d0)));
            float2 t1 = relu2(ffma2(u0, hA0, ffma2(ub, hA1, ffma2(uc, hA2, d1))));
            float2 t2 = relu2(ffma2(u0, hA1, ffma2(ub, hA2, d2v)));
            float2 sA = fadd2(fadd2(t0, t1), t2);
            t0 = relu2(ffma2(ub, hB0, ffma2(uc, hB1, d0)));
            t1 = relu2(ffma2(u0, hB0, ffma2(ub, hB1, ffma2(uc, hB2, d1))));
            t2 = relu2(ffma2(u0, hB1, ffma2(ub, hB2, d2v)));
            float2 sB = fadd2(fadd2(t0, t1), t2);
#pragma unroll
            for (int k = 0; k < 8; k++) {
                float4 wq = sfw4[oc*8 + k];
                float2 w0 = make_float2(wq.x, wq.y), w1v = make_float2(wq.z, wq.w);
                fA[2*k]   = ffma2(w0,  sA, fA[2*k]);
                fA[2*k+1] = ffma2(w1v, sA, fA[2*k+1]);
                fB[2*k]   = ffma2(w0,  sB, fB[2*k]);
                fB[2*k+1] = ffma2(w1v, sB, fB[2*k+1]);
            }
        }
    }

    float o0 = fb2v, o1 = fb2v, o2 = fb2v, o3 = fb2v;
#pragma unroll
    for (int j = 0; j < 16; j++) {
        float wj = sfw2[j];
        o0 = fmaf(wj, fmaxf(fA[j].x, 0.f), o0);
        o1 = fmaf(wj, fmaxf(fA[j].y, 0.f), o1);
        o2 = fmaf(wj, fmaxf(fB[j].x, 0.f), o2);
        o3 = fmaf(wj, fmaxf(fB[j].y, 0.f), o3);
    }
    reinterpret_cast<float4*>(out)[g2] = make_float4(o0, o1, o2, o3);
}

extern "C" void kernel_launch(void* const* d_in, const int* in_sizes, int n_in,
                              void* d_out, int out_size) {
    const float* x   = (const float*)d_in[0];
    const float* w1  = (const float*)d_in[1];
    const float* b1  = (const float*)d_in[2];
    const float* g1  = (const float*)d_in[3];
    const float* bt1 = (const float*)d_in[4];
    const float* w2  = (const float*)d_in[5];
    const float* b2  = (const float*)d_in[6];
    const float* g2v = (const float*)d_in[7];
    const float* bt2 = (const float*)d_in[8];
    const float* fw1 = (const float*)d_in[9];
    const float* fb1 = (const float*)d_in[10];
    const float* fw2 = (const float*)d_in[11];
    const float* fb2 = (const float*)d_in[12];
    float* out = (float*)d_out;

    void* accs_ptr = nullptr;
    cudaGetSymbolAddress(&accs_ptr, g_accs);
    cudaMemsetAsync(accs_ptr, 0, 96 * sizeof(float));

    dim3 g1d(256, 4);
    pass1_kernel<<<g1d, 256>>>(x, w1, b1);
    dim3 g2d(256, 8);
    pass2_kernel<<<g2d, 256>>>(x, w1, b1, g1, bt1, w2, b2);
    pass3_kernel<<<NGROUPS / 256, 256>>>(x, w1, b1, g1, bt1, w2, b2,
                                         g2v, bt2, fw1, fb1, fw2, fb2, out);
}